// round 10
// baseline (speedup 1.0000x reference)
#include <cuda_runtime.h>

#ifndef BATCH_THREADS
#define BATCH_THREADS 128
#endif

__global__ void __launch_bounds__(BATCH_THREADS, 14)
transop_expm_kernel(const float* __restrict__ c,
                    const float* __restrict__ x,
                    const float* __restrict__ psi,
                    float* __restrict__ out,
                    int B) {
    __shared__ float sp[54];
    if (threadIdx.x < 54) sp[threadIdx.x] = psi[threadIdx.x];
    __syncthreads();

    int b = blockIdx.x * BATCH_THREADS + threadIdx.x;
    if (b >= B) return;

    // ---- front-batched global loads: c (3x LDG.64) and x (3x LDG.32) ----
    // Issuing x here lets its DRAM latency overlap the entire expm chain.
    const float2* c2 = reinterpret_cast<const float2*>(c);
    float2 ca = c2[3 * b + 0];
    float2 cb = c2[3 * b + 1];
    float2 cd = c2[3 * b + 2];
    float x0 = x[3 * b + 0];
    float x1 = x[3 * b + 1];
    float x2 = x[3 * b + 2];
    float cc0 = ca.x, cc1 = ca.y, cc2 = cb.x, cc3 = cb.y, cc4 = cd.x, cc5 = cd.y;

    // ---- T = sum_m cc[m] * psi[m]  (54 FMA, broadcast LDS) ----
    float T[9];
#pragma unroll
    for (int p = 0; p < 9; p++) {
        float s = cc0 * sp[p];
        s = fmaf(cc1, sp[9 + p], s);
        s = fmaf(cc2, sp[18 + p], s);
        s = fmaf(cc3, sp[27 + p], s);
        s = fmaf(cc4, sp[36 + p], s);
        s = fmaf(cc5, sp[45 + p], s);
        T[p] = s;
    }

    // ---- split: T = mu*I + T0 (traceless) ----
    float mu = (T[0] + T[4] + T[8]) * (1.0f / 3.0f);
    T[0] -= mu;
    T[4] -= mu;
    T[8] -= mu;

    // ---- char poly of T0:  T0^3 = p*T0 + q*I ----
    float u = T[0] * T[0];
    u = fmaf(T[4], T[4], u);
    u = fmaf(T[8], T[8], u);
    float v = T[1] * T[3];
    v = fmaf(T[2], T[6], v);
    v = fmaf(T[5], T[7], v);
    float pc = fmaf(0.5f, u, v);

    float m0 = fmaf(T[4], T[8], -T[5] * T[7]);
    float m1 = fmaf(T[5], T[6], -T[3] * T[8]);
    float m2 = fmaf(T[3], T[7], -T[4] * T[6]);
    float qc = T[0] * m0;
    qc = fmaf(T[1], m1, qc);
    qc = fmaf(T[2], m2, qc);

    // ---- Y = T0/8: pY = p/64, qY = q/512 ----
    float pY = pc * (1.0f / 64.0f);
    float qY = qc * (1.0f / 512.0f);

    // ---- exp(Y) mod (X^3 - pY X - qY), Horner deg-9 ----
    float s0 = 1.0f / 362880.0f;  // 1/9!
    float s1 = 0.0f, s2 = 0.0f;
    const float w[9] = {1.0f,
                        1.0f,
                        1.0f / 2.0f,
                        1.0f / 6.0f,
                        1.0f / 24.0f,
                        1.0f / 120.0f,
                        1.0f / 720.0f,
                        1.0f / 5040.0f,
                        1.0f / 40320.0f};  // 1/k!, k=0..8
#pragma unroll
    for (int k = 8; k >= 0; k--) {
        float n0 = fmaf(s2, qY, w[k]);
        float n1 = fmaf(s2, pY, s0);
        s2 = s1;
        s0 = n0;
        s1 = n1;
    }

    // ---- 3 squarings in coefficient space: exp(2Y), exp(4Y), exp(8Y) ----
#pragma unroll
    for (int i = 0; i < 3; i++) {
        float d0 = s0 + s0;
        float b0 = s0 * s0;
        float b1 = d0 * s1;
        float b2 = fmaf(s1, s1, d0 * s2);
        float b3 = (s1 + s1) * s2;
        float b4 = s2 * s2;
        s0 = fmaf(qY, b3, b0);
        s1 = fmaf(pY, b3, fmaf(qY, b4, b1));
        s2 = fmaf(pY, b4, b2);
    }
    // exp(T0) = s0*I + s1*Y + s2*Y^2, Y = T0/8

    // ---- fold e^mu and basis scales ----
    float emu = __expf(mu);
    float g0 = s0 * emu;
    float g1 = s1 * emu * 0.125f;
    float g2 = s2 * emu * 0.015625f;

    // ---- y = g0*x + g1*(T0 x) + g2*(T0 (T0 x)) ----
    float v0 = fmaf(T[0], x0, fmaf(T[1], x1, T[2] * x2));
    float v1 = fmaf(T[3], x0, fmaf(T[4], x1, T[5] * x2));
    float v2 = fmaf(T[6], x0, fmaf(T[7], x1, T[8] * x2));

    float w0 = fmaf(T[0], v0, fmaf(T[1], v1, T[2] * v2));
    float w1 = fmaf(T[3], v0, fmaf(T[4], v1, T[5] * v2));
    float w2 = fmaf(T[6], v0, fmaf(T[7], v1, T[8] * v2));

    float y0 = fmaf(g0, x0, fmaf(g1, v0, g2 * w0));
    float y1 = fmaf(g0, x1, fmaf(g1, v1, g2 * w1));
    float y2 = fmaf(g0, x2, fmaf(g1, v2, g2 * w2));

    out[3 * b + 0] = y0;
    out[3 * b + 1] = y1;
    out[3 * b + 2] = y2;
}

extern "C" void kernel_launch(void* const* d_in, const int* in_sizes, int n_in,
                              void* d_out, int out_size) {
    // Identify inputs by element count: psi=54, c=B*6, x=B*3
    const float* c = nullptr;
    const float* x = nullptr;
    const float* psi = nullptr;
    long long maxsz = 0;
    for (int i = 0; i < n_in; i++)
        if ((long long)in_sizes[i] > maxsz) maxsz = in_sizes[i];
    int B = (int)(maxsz / 6);
    for (int i = 0; i < n_in; i++) {
        if (in_sizes[i] == 54) psi = (const float*)d_in[i];
        else if (in_sizes[i] == B * 6) c = (const float*)d_in[i];
        else if (in_sizes[i] == B * 3) x = (const float*)d_in[i];
    }

    float* out = (float*)d_out;
    int grid = (B + BATCH_THREADS - 1) / BATCH_THREADS;
    transop_expm_kernel<<<grid, BATCH_THREADS>>>(c, x, psi, out, B);
}

// round 11
// speedup vs baseline: 1.0710x; 1.0710x over previous
#include <cuda_runtime.h>

#ifndef BATCH_THREADS
#define BATCH_THREADS 256
#endif

__global__ void __launch_bounds__(BATCH_THREADS, 6)
transop_expm_kernel(const float* __restrict__ c,
                    const float* __restrict__ x,
                    const float* __restrict__ psi,
                    float* __restrict__ out,
                    int B) {
    // psi pair-packed: sp2[p*4 + j] = (psi[2j][p], psi[2j+1][p]), j=0..2
    // (rows padded to 4 float2 = 32B). T-build becomes 27 LDS.64 broadcasts.
    __shared__ float2 sp2[36];
    if (threadIdx.x < 27) {
        int p = threadIdx.x / 3;
        int j = threadIdx.x % 3;
        sp2[p * 4 + j] = make_float2(psi[(2 * j) * 9 + p], psi[(2 * j + 1) * 9 + p]);
    }
    __syncthreads();

    int b = blockIdx.x * BATCH_THREADS + threadIdx.x;
    if (b >= B) return;

    // ---- c[b,0..5]: three LDG.64 ----
    const float2* c2 = reinterpret_cast<const float2*>(c);
    float2 ca = c2[3 * b + 0];
    float2 cb = c2[3 * b + 1];
    float2 cd = c2[3 * b + 2];
    float cc0 = ca.x, cc1 = ca.y, cc2 = cb.x, cc3 = cb.y, cc4 = cd.x, cc5 = cd.y;

    // ---- T = sum_m cc[m] * psi[m]  (54 FMA, 27 LDS.64) ----
    float T[9];
#pragma unroll
    for (int p = 0; p < 9; p++) {
        float2 w01 = sp2[p * 4 + 0];
        float2 w23 = sp2[p * 4 + 1];
        float2 w45 = sp2[p * 4 + 2];
        float s = cc0 * w01.x;
        s = fmaf(cc1, w01.y, s);
        s = fmaf(cc2, w23.x, s);
        s = fmaf(cc3, w23.y, s);
        s = fmaf(cc4, w45.x, s);
        s = fmaf(cc5, w45.y, s);
        T[p] = s;
    }

    // ---- split: T = mu*I + T0 (traceless) ----
    float mu = (T[0] + T[4] + T[8]) * (1.0f / 3.0f);
    T[0] -= mu;
    T[4] -= mu;
    T[8] -= mu;

    // ---- char poly of T0:  T0^3 = p*T0 + q*I ----
    float u = T[0] * T[0];
    u = fmaf(T[4], T[4], u);
    u = fmaf(T[8], T[8], u);
    float v = T[1] * T[3];
    v = fmaf(T[2], T[6], v);
    v = fmaf(T[5], T[7], v);
    float pc = fmaf(0.5f, u, v);

    float m0 = fmaf(T[4], T[8], -T[5] * T[7]);
    float m1 = fmaf(T[5], T[6], -T[3] * T[8]);
    float m2 = fmaf(T[3], T[7], -T[4] * T[6]);
    float qc = T[0] * m0;
    qc = fmaf(T[1], m1, qc);
    qc = fmaf(T[2], m2, qc);

    // ---- Y = T0/8: pY = p/64, qY = q/512 ----
    float pY = pc * (1.0f / 64.0f);
    float qY = qc * (1.0f / 512.0f);

    // ---- x loads hoisted here: ~150 cycles of Horner/squaring below cover
    //      most of the DRAM latency before the matvec needs them ----
    float x0 = x[3 * b + 0];
    float x1 = x[3 * b + 1];
    float x2 = x[3 * b + 2];

    // ---- exp(Y) mod (X^3 - pY X - qY), Horner deg-9 ----
    float s0 = 1.0f / 362880.0f;  // 1/9!
    float s1 = 0.0f, s2 = 0.0f;
    const float w[9] = {1.0f,
                        1.0f,
                        1.0f / 2.0f,
                        1.0f / 6.0f,
                        1.0f / 24.0f,
                        1.0f / 120.0f,
                        1.0f / 720.0f,
                        1.0f / 5040.0f,
                        1.0f / 40320.0f};  // 1/k!, k=0..8
#pragma unroll
    for (int k = 8; k >= 0; k--) {
        float n0 = fmaf(s2, qY, w[k]);
        float n1 = fmaf(s2, pY, s0);
        s2 = s1;
        s0 = n0;
        s1 = n1;
    }

    // ---- 3 squarings in coefficient space: exp(2Y), exp(4Y), exp(8Y) ----
#pragma unroll
    for (int i = 0; i < 3; i++) {
        float d0 = s0 + s0;
        float b0 = s0 * s0;
        float b1 = d0 * s1;
        float b2 = fmaf(s1, s1, d0 * s2);
        float b3 = (s1 + s1) * s2;
        float b4 = s2 * s2;
        s0 = fmaf(qY, b3, b0);
        s1 = fmaf(pY, b3, fmaf(qY, b4, b1));
        s2 = fmaf(pY, b4, b2);
    }
    // exp(T0) = s0*I + s1*Y + s2*Y^2, Y = T0/8

    // ---- fold e^mu and basis scales ----
    float emu = __expf(mu);
    float g0 = s0 * emu;
    float g1 = s1 * emu * 0.125f;
    float g2 = s2 * emu * 0.015625f;

    // ---- y = g0*x + g1*(T0 x) + g2*(T0 (T0 x)) ----
    float v0 = fmaf(T[0], x0, fmaf(T[1], x1, T[2] * x2));
    float v1 = fmaf(T[3], x0, fmaf(T[4], x1, T[5] * x2));
    float v2 = fmaf(T[6], x0, fmaf(T[7], x1, T[8] * x2));

    float w0 = fmaf(T[0], v0, fmaf(T[1], v1, T[2] * v2));
    float w1 = fmaf(T[3], v0, fmaf(T[4], v1, T[5] * v2));
    float w2 = fmaf(T[6], v0, fmaf(T[7], v1, T[8] * v2));

    float y0 = fmaf(g0, x0, fmaf(g1, v0, g2 * w0));
    float y1 = fmaf(g0, x1, fmaf(g1, v1, g2 * w1));
    float y2 = fmaf(g0, x2, fmaf(g1, v2, g2 * w2));

    out[3 * b + 0] = y0;
    out[3 * b + 1] = y1;
    out[3 * b + 2] = y2;
}

extern "C" void kernel_launch(void* const* d_in, const int* in_sizes, int n_in,
                              void* d_out, int out_size) {
    // Identify inputs by element count: psi=54, c=B*6, x=B*3
    const float* c = nullptr;
    const float* x = nullptr;
    const float* psi = nullptr;
    long long maxsz = 0;
    for (int i = 0; i < n_in; i++)
        if ((long long)in_sizes[i] > maxsz) maxsz = in_sizes[i];
    int B = (int)(maxsz / 6);
    for (int i = 0; i < n_in; i++) {
        if (in_sizes[i] == 54) psi = (const float*)d_in[i];
        else if (in_sizes[i] == B * 6) c = (const float*)d_in[i];
        else if (in_sizes[i] == B * 3) x = (const float*)d_in[i];
    }

    float* out = (float*)d_out;
    int grid = (B + BATCH_THREADS - 1) / BATCH_THREADS;
    transop_expm_kernel<<<grid, BATCH_THREADS>>>(c, x, psi, out, B);
}

// round 12
// speedup vs baseline: 1.1104x; 1.0368x over previous
#include <cuda_runtime.h>

#ifndef BATCH_THREADS
#define BATCH_THREADS 256
#endif
#define GRID_BLOCKS 740  // 5 blocks/SM x 148 SMs (persistent fill)

__global__ void __launch_bounds__(BATCH_THREADS, 5)
transop_expm_kernel(const float* __restrict__ c,
                    const float* __restrict__ x,
                    const float* __restrict__ psi,
                    float* __restrict__ out,
                    int B) {
    __shared__ float sp[54];
    if (threadIdx.x < 54) sp[threadIdx.x] = psi[threadIdx.x];
    __syncthreads();

    const int stride = GRID_BLOCKS * BATCH_THREADS;
    int b = blockIdx.x * BATCH_THREADS + threadIdx.x;
    if (b >= B) return;

    const float2* c2 = reinterpret_cast<const float2*>(c);

    // ---- prologue: load item b ----
    float2 ca = c2[3 * b + 0];
    float2 cb = c2[3 * b + 1];
    float2 cd = c2[3 * b + 2];
    float px0 = x[3 * b + 0];
    float px1 = x[3 * b + 1];
    float px2 = x[3 * b + 2];

    while (true) {
        // working copies of current item
        float cc0 = ca.x, cc1 = ca.y, cc2 = cb.x, cc3 = cb.y, cc4 = cd.x, cc5 = cd.y;
        float x0 = px0, x1 = px1, x2 = px2;

        // ---- prefetch next item (overlaps the whole compute chain below) ----
        int bn = b + stride;
        bool more = bn < B;
        if (more) {
            ca = c2[3 * bn + 0];
            cb = c2[3 * bn + 1];
            cd = c2[3 * bn + 2];
            px0 = x[3 * bn + 0];
            px1 = x[3 * bn + 1];
            px2 = x[3 * bn + 2];
        }

        // ---- T = sum_m cc[m] * psi[m]  (54 FMA, broadcast LDS) ----
        float T[9];
#pragma unroll
        for (int p = 0; p < 9; p++) {
            float s = cc0 * sp[p];
            s = fmaf(cc1, sp[9 + p], s);
            s = fmaf(cc2, sp[18 + p], s);
            s = fmaf(cc3, sp[27 + p], s);
            s = fmaf(cc4, sp[36 + p], s);
            s = fmaf(cc5, sp[45 + p], s);
            T[p] = s;
        }

        // ---- split: T = mu*I + T0 (traceless) ----
        float mu = (T[0] + T[4] + T[8]) * (1.0f / 3.0f);
        T[0] -= mu;
        T[4] -= mu;
        T[8] -= mu;

        // ---- char poly of T0:  T0^3 = p*T0 + q*I ----
        float u = T[0] * T[0];
        u = fmaf(T[4], T[4], u);
        u = fmaf(T[8], T[8], u);
        float v = T[1] * T[3];
        v = fmaf(T[2], T[6], v);
        v = fmaf(T[5], T[7], v);
        float pc = fmaf(0.5f, u, v);

        float m0 = fmaf(T[4], T[8], -T[5] * T[7]);
        float m1 = fmaf(T[5], T[6], -T[3] * T[8]);
        float m2 = fmaf(T[3], T[7], -T[4] * T[6]);
        float qc = T[0] * m0;
        qc = fmaf(T[1], m1, qc);
        qc = fmaf(T[2], m2, qc);

        // ---- Y = T0/8: pY = p/64, qY = q/512 ----
        float pY = pc * (1.0f / 64.0f);
        float qY = qc * (1.0f / 512.0f);

        // ---- exp(Y) mod (X^3 - pY X - qY), Horner deg-9 ----
        float s0 = 1.0f / 362880.0f;  // 1/9!
        float s1 = 0.0f, s2 = 0.0f;
        const float w[9] = {1.0f,
                            1.0f,
                            1.0f / 2.0f,
                            1.0f / 6.0f,
                            1.0f / 24.0f,
                            1.0f / 120.0f,
                            1.0f / 720.0f,
                            1.0f / 5040.0f,
                            1.0f / 40320.0f};  // 1/k!, k=0..8
#pragma unroll
        for (int k = 8; k >= 0; k--) {
            float n0 = fmaf(s2, qY, w[k]);
            float n1 = fmaf(s2, pY, s0);
            s2 = s1;
            s0 = n0;
            s1 = n1;
        }

        // ---- 3 squarings in coefficient space ----
#pragma unroll
        for (int i = 0; i < 3; i++) {
            float d0 = s0 + s0;
            float b0 = s0 * s0;
            float b1 = d0 * s1;
            float b2 = fmaf(s1, s1, d0 * s2);
            float b3 = (s1 + s1) * s2;
            float b4 = s2 * s2;
            s0 = fmaf(qY, b3, b0);
            s1 = fmaf(pY, b3, fmaf(qY, b4, b1));
            s2 = fmaf(pY, b4, b2);
        }
        // exp(T0) = s0*I + s1*Y + s2*Y^2, Y = T0/8

        // ---- fold e^mu and basis scales ----
        float emu = __expf(mu);
        float g0 = s0 * emu;
        float g1 = s1 * emu * 0.125f;
        float g2 = s2 * emu * 0.015625f;

        // ---- y = g0*x + g1*(T0 x) + g2*(T0 (T0 x)) ----
        float v0 = fmaf(T[0], x0, fmaf(T[1], x1, T[2] * x2));
        float v1 = fmaf(T[3], x0, fmaf(T[4], x1, T[5] * x2));
        float v2 = fmaf(T[6], x0, fmaf(T[7], x1, T[8] * x2));

        float w0 = fmaf(T[0], v0, fmaf(T[1], v1, T[2] * v2));
        float w1 = fmaf(T[3], v0, fmaf(T[4], v1, T[5] * v2));
        float w2 = fmaf(T[6], v0, fmaf(T[7], v1, T[8] * v2));

        float y0 = fmaf(g0, x0, fmaf(g1, v0, g2 * w0));
        float y1 = fmaf(g0, x1, fmaf(g1, v1, g2 * w1));
        float y2 = fmaf(g0, x2, fmaf(g1, v2, g2 * w2));

        out[3 * b + 0] = y0;
        out[3 * b + 1] = y1;
        out[3 * b + 2] = y2;

        if (!more) break;
        b = bn;
    }
}

extern "C" void kernel_launch(void* const* d_in, const int* in_sizes, int n_in,
                              void* d_out, int out_size) {
    // Identify inputs by element count: psi=54, c=B*6, x=B*3
    const float* c = nullptr;
    const float* x = nullptr;
    const float* psi = nullptr;
    long long maxsz = 0;
    for (int i = 0; i < n_in; i++)
        if ((long long)in_sizes[i] > maxsz) maxsz = in_sizes[i];
    int B = (int)(maxsz / 6);
    for (int i = 0; i < n_in; i++) {
        if (in_sizes[i] == 54) psi = (const float*)d_in[i];
        else if (in_sizes[i] == B * 6) c = (const float*)d_in[i];
        else if (in_sizes[i] == B * 3) x = (const float*)d_in[i];
    }

    float* out = (float*)d_out;
    transop_expm_kernel<<<GRID_BLOCKS, BATCH_THREADS>>>(c, x, psi, out, B);
}

// round 13
// speedup vs baseline: 1.1425x; 1.0290x over previous
#include <cuda_runtime.h>

#ifndef BATCH_THREADS
#define BATCH_THREADS 256
#endif
#define GRID_BLOCKS 740  // 5 blocks/SM x 148 SMs (persistent fill)

__global__ void __launch_bounds__(BATCH_THREADS, 5)
transop_expm_kernel(const float* __restrict__ c,
                    const float* __restrict__ x,
                    const float* __restrict__ psi,
                    float* __restrict__ out,
                    int B) {
    __shared__ float sp[54];
    if (threadIdx.x < 54) sp[threadIdx.x] = psi[threadIdx.x];
    __syncthreads();

    const int stride = GRID_BLOCKS * BATCH_THREADS;
    int b = blockIdx.x * BATCH_THREADS + threadIdx.x;
    if (b >= B) return;

    // pointer-increment addressing (no per-iter 3*b IMADs)
    const float2* cp = reinterpret_cast<const float2*>(c) + 3 * (long long)b;
    const float*  xp = x + 3 * (long long)b;
    float*        op = out + 3 * (long long)b;
    const long long cstep = 3LL * stride;  // in float2
    const long long xstep = 3LL * stride;  // in float

    // ---- prologue: load item b (streaming: touched once) ----
    float2 ca = __ldcs(cp + 0);
    float2 cb = __ldcs(cp + 1);
    float2 cd = __ldcs(cp + 2);
    float px0 = __ldcs(xp + 0);
    float px1 = __ldcs(xp + 1);
    float px2 = __ldcs(xp + 2);

    while (true) {
        // working copies of current item
        float cc0 = ca.x, cc1 = ca.y, cc2 = cb.x, cc3 = cb.y, cc4 = cd.x, cc5 = cd.y;
        float x0 = px0, x1 = px1, x2 = px2;

        // ---- prefetch next item (overlaps the compute chain below) ----
        int bn = b + stride;
        bool more = bn < B;
        if (more) {
            cp += cstep;
            xp += xstep;
            ca = __ldcs(cp + 0);
            cb = __ldcs(cp + 1);
            cd = __ldcs(cp + 2);
            px0 = __ldcs(xp + 0);
            px1 = __ldcs(xp + 1);
            px2 = __ldcs(xp + 2);
        }

        // ---- T = sum_m cc[m] * psi[m]  (54 FMA, broadcast LDS) ----
        float T[9];
#pragma unroll
        for (int p = 0; p < 9; p++) {
            float s = cc0 * sp[p];
            s = fmaf(cc1, sp[9 + p], s);
            s = fmaf(cc2, sp[18 + p], s);
            s = fmaf(cc3, sp[27 + p], s);
            s = fmaf(cc4, sp[36 + p], s);
            s = fmaf(cc5, sp[45 + p], s);
            T[p] = s;
        }

        // ---- split: T = mu*I + T0 (traceless) ----
        float mu = (T[0] + T[4] + T[8]) * (1.0f / 3.0f);
        T[0] -= mu;
        T[4] -= mu;
        T[8] -= mu;

        // ---- char poly of T0:  T0^3 = p*T0 + q*I ----
        float u = T[0] * T[0];
        u = fmaf(T[4], T[4], u);
        u = fmaf(T[8], T[8], u);
        float v = T[1] * T[3];
        v = fmaf(T[2], T[6], v);
        v = fmaf(T[5], T[7], v);
        float pc = fmaf(0.5f, u, v);

        float m0 = fmaf(T[4], T[8], -T[5] * T[7]);
        float m1 = fmaf(T[5], T[6], -T[3] * T[8]);
        float m2 = fmaf(T[3], T[7], -T[4] * T[6]);
        float qc = T[0] * m0;
        qc = fmaf(T[1], m1, qc);
        qc = fmaf(T[2], m2, qc);

        // ---- Y = T0/4: pY = p/16, qY = q/64 ----
        float pY = pc * (1.0f / 16.0f);
        float qY = qc * (1.0f / 64.0f);

        // ---- exp(Y) mod (X^3 - pY X - qY), Horner deg-10 ----
        float s0 = 1.0f / 3628800.0f;  // 1/10!
        float s1 = 0.0f, s2 = 0.0f;
        const float w[10] = {1.0f,
                             1.0f,
                             1.0f / 2.0f,
                             1.0f / 6.0f,
                             1.0f / 24.0f,
                             1.0f / 120.0f,
                             1.0f / 720.0f,
                             1.0f / 5040.0f,
                             1.0f / 40320.0f,
                             1.0f / 362880.0f};  // 1/k!, k=0..9
#pragma unroll
        for (int k = 9; k >= 0; k--) {
            float n0 = fmaf(s2, qY, w[k]);
            float n1 = fmaf(s2, pY, s0);
            s2 = s1;
            s0 = n0;
            s1 = n1;
        }

        // ---- 2 squarings in coefficient space: exp(2Y), exp(4Y) ----
#pragma unroll
        for (int i = 0; i < 2; i++) {
            float d0 = s0 + s0;
            float b0 = s0 * s0;
            float b1 = d0 * s1;
            float b2 = fmaf(s1, s1, d0 * s2);
            float b3 = (s1 + s1) * s2;
            float b4 = s2 * s2;
            s0 = fmaf(qY, b3, b0);
            s1 = fmaf(pY, b3, fmaf(qY, b4, b1));
            s2 = fmaf(pY, b4, b2);
        }
        // exp(T0) = s0*I + s1*Y + s2*Y^2, Y = T0/4

        // ---- fold e^mu and basis scales (Y = T0/4 -> 1/4, 1/16) ----
        float emu = __expf(mu);
        float g0 = s0 * emu;
        float g1 = s1 * emu * 0.25f;
        float g2 = s2 * emu * 0.0625f;

        // ---- y = g0*x + g1*(T0 x) + g2*(T0 (T0 x)) ----
        float v0 = fmaf(T[0], x0, fmaf(T[1], x1, T[2] * x2));
        float v1 = fmaf(T[3], x0, fmaf(T[4], x1, T[5] * x2));
        float v2 = fmaf(T[6], x0, fmaf(T[7], x1, T[8] * x2));

        float w0 = fmaf(T[0], v0, fmaf(T[1], v1, T[2] * v2));
        float w1 = fmaf(T[3], v0, fmaf(T[4], v1, T[5] * v2));
        float w2 = fmaf(T[6], v0, fmaf(T[7], v1, T[8] * v2));

        float y0 = fmaf(g0, x0, fmaf(g1, v0, g2 * w0));
        float y1 = fmaf(g0, x1, fmaf(g1, v1, g2 * w1));
        float y2 = fmaf(g0, x2, fmaf(g1, v2, g2 * w2));

        __stcs(op + 0, y0);
        __stcs(op + 1, y1);
        __stcs(op + 2, y2);

        if (!more) break;
        b = bn;
        op += xstep;
    }
}

extern "C" void kernel_launch(void* const* d_in, const int* in_sizes, int n_in,
                              void* d_out, int out_size) {
    // Identify inputs by element count: psi=54, c=B*6, x=B*3
    const float* c = nullptr;
    const float* x = nullptr;
    const float* psi = nullptr;
    long long maxsz = 0;
    for (int i = 0; i < n_in; i++)
        if ((long long)in_sizes[i] > maxsz) maxsz = in_sizes[i];
    int B = (int)(maxsz / 6);
    for (int i = 0; i < n_in; i++) {
        if (in_sizes[i] == 54) psi = (const float*)d_in[i];
        else if (in_sizes[i] == B * 6) c = (const float*)d_in[i];
        else if (in_sizes[i] == B * 3) x = (const float*)d_in[i];
    }

    float* out = (float*)d_out;
    transop_expm_kernel<<<GRID_BLOCKS, BATCH_THREADS>>>(c, x, psi, out, B);
}

// round 14
// speedup vs baseline: 1.1633x; 1.0181x over previous
#include <cuda_runtime.h>

#define NTHREADS 128
#define NBLOCKS 740  // 148 SMs x 5 blocks (persistent fill; harmless if SM count differs)

__global__ void __launch_bounds__(NTHREADS, 5)
transop_expm_kernel(const float* __restrict__ c,
                    const float* __restrict__ x,
                    const float* __restrict__ psi,
                    float* __restrict__ out,
                    int B) {
    // ---- psi resident in REGISTERS (54 floats) — zero LDS in the hot loop.
    // All threads read the same 54 values: LDG broadcast, L1-hit after first warp.
    float P[54];
#pragma unroll
    for (int i = 0; i < 54; i++) P[i] = __ldg(&psi[i]);

    const int stride = NBLOCKS * NTHREADS;
    int b = blockIdx.x * NTHREADS + threadIdx.x;
    if (b >= B) return;

    const float2* cp = reinterpret_cast<const float2*>(c) + 3 * b;
    const float*  xp = x + 3 * b;
    float*        op = out + 3 * b;
    const int cstep = 3 * stride;  // float2 units
    const int xstep = 3 * stride;  // float units

    // ---- prologue: load item b (streaming) ----
    float2 ca = __ldcs(cp + 0);
    float2 cb = __ldcs(cp + 1);
    float2 cd = __ldcs(cp + 2);
    float px0 = __ldcs(xp + 0);
    float px1 = __ldcs(xp + 1);
    float px2 = __ldcs(xp + 2);

    while (true) {
        float cc0 = ca.x, cc1 = ca.y, cc2 = cb.x, cc3 = cb.y, cc4 = cd.x, cc5 = cd.y;
        float x0 = px0, x1 = px1, x2 = px2;

        // ---- prefetch next item (overlaps entire compute chain) ----
        int bn = b + stride;
        bool more = bn < B;
        if (more) {
            cp += cstep;
            xp += xstep;
            ca = __ldcs(cp + 0);
            cb = __ldcs(cp + 1);
            cd = __ldcs(cp + 2);
            px0 = __ldcs(xp + 0);
            px1 = __ldcs(xp + 1);
            px2 = __ldcs(xp + 2);
        }

        // ---- T = sum_m cc[m] * psi[m]  (54 FMA, all-register operands) ----
        float T[9];
#pragma unroll
        for (int p = 0; p < 9; p++) {
            float s = cc0 * P[p];
            s = fmaf(cc1, P[9 + p], s);
            s = fmaf(cc2, P[18 + p], s);
            s = fmaf(cc3, P[27 + p], s);
            s = fmaf(cc4, P[36 + p], s);
            s = fmaf(cc5, P[45 + p], s);
            T[p] = s;
        }

        // ---- split: T = mu*I + T0 (traceless) ----
        float mu = (T[0] + T[4] + T[8]) * (1.0f / 3.0f);
        T[0] -= mu;
        T[4] -= mu;
        T[8] -= mu;

        // ---- char poly of T0:  T0^3 = p*T0 + q*I ----
        float u = T[0] * T[0];
        u = fmaf(T[4], T[4], u);
        u = fmaf(T[8], T[8], u);
        float v = T[1] * T[3];
        v = fmaf(T[2], T[6], v);
        v = fmaf(T[5], T[7], v);
        float pc = fmaf(0.5f, u, v);

        float m0 = fmaf(T[4], T[8], -T[5] * T[7]);
        float m1 = fmaf(T[5], T[6], -T[3] * T[8]);
        float m2 = fmaf(T[3], T[7], -T[4] * T[6]);
        float qc = T[0] * m0;
        qc = fmaf(T[1], m1, qc);
        qc = fmaf(T[2], m2, qc);

        // ---- Y = T0/4: pY = p/16, qY = q/64 ----
        float pY = pc * (1.0f / 16.0f);
        float qY = qc * (1.0f / 64.0f);

        // ---- exp(Y) mod (X^3 - pY X - qY), Horner deg-10 ----
        float s0 = 1.0f / 3628800.0f;  // 1/10!
        float s1 = 0.0f, s2 = 0.0f;
        const float w[10] = {1.0f,
                             1.0f,
                             1.0f / 2.0f,
                             1.0f / 6.0f,
                             1.0f / 24.0f,
                             1.0f / 120.0f,
                             1.0f / 720.0f,
                             1.0f / 5040.0f,
                             1.0f / 40320.0f,
                             1.0f / 362880.0f};  // 1/k!, k=0..9
#pragma unroll
        for (int k = 9; k >= 0; k--) {
            float n0 = fmaf(s2, qY, w[k]);
            float n1 = fmaf(s2, pY, s0);
            s2 = s1;
            s0 = n0;
            s1 = n1;
        }

        // ---- 2 squarings in coefficient space: exp(2Y), exp(4Y) ----
#pragma unroll
        for (int i = 0; i < 2; i++) {
            float d0 = s0 + s0;
            float b0 = s0 * s0;
            float b1 = d0 * s1;
            float b2 = fmaf(s1, s1, d0 * s2);
            float b3 = (s1 + s1) * s2;
            float b4 = s2 * s2;
            s0 = fmaf(qY, b3, b0);
            s1 = fmaf(pY, b3, fmaf(qY, b4, b1));
            s2 = fmaf(pY, b4, b2);
        }
        // exp(T0) = s0*I + s1*Y + s2*Y^2, Y = T0/4

        // ---- fold e^mu and basis scales ----
        float emu = __expf(mu);
        float g0 = s0 * emu;
        float g1 = s1 * emu * 0.25f;
        float g2 = s2 * emu * 0.0625f;

        // ---- y = g0*x + g1*(T0 x) + g2*(T0 (T0 x)) ----
        float v0 = fmaf(T[0], x0, fmaf(T[1], x1, T[2] * x2));
        float v1 = fmaf(T[3], x0, fmaf(T[4], x1, T[5] * x2));
        float v2 = fmaf(T[6], x0, fmaf(T[7], x1, T[8] * x2));

        float w0 = fmaf(T[0], v0, fmaf(T[1], v1, T[2] * v2));
        float w1 = fmaf(T[3], v0, fmaf(T[4], v1, T[5] * v2));
        float w2 = fmaf(T[6], v0, fmaf(T[7], v1, T[8] * v2));

        float y0 = fmaf(g0, x0, fmaf(g1, v0, g2 * w0));
        float y1 = fmaf(g0, x1, fmaf(g1, v1, g2 * w1));
        float y2 = fmaf(g0, x2, fmaf(g1, v2, g2 * w2));

        __stcs(op + 0, y0);
        __stcs(op + 1, y1);
        __stcs(op + 2, y2);

        if (!more) break;
        b = bn;
        op += xstep;
    }
}

extern "C" void kernel_launch(void* const* d_in, const int* in_sizes, int n_in,
                              void* d_out, int out_size) {
    // Identify inputs by element count: psi=54, c=B*6, x=B*3
    const float* c = nullptr;
    const float* x = nullptr;
    const float* psi = nullptr;
    long long maxsz = 0;
    for (int i = 0; i < n_in; i++)
        if ((long long)in_sizes[i] > maxsz) maxsz = in_sizes[i];
    int B = (int)(maxsz / 6);
    for (int i = 0; i < n_in; i++) {
        if (in_sizes[i] == 54) psi = (const float*)d_in[i];
        else if (in_sizes[i] == B * 6) c = (const float*)d_in[i];
        else if (in_sizes[i] == B * 3) x = (const float*)d_in[i];
    }

    float* out = (float*)d_out;
    transop_expm_kernel<<<NBLOCKS, NTHREADS>>>(c, x, psi, out, B);
}